// round 6
// baseline (speedup 1.0000x reference)
#include <cuda_runtime.h>
#include <cstdint>

#define N_NODE 50000
#define N_EDGE 800000
#define HID 128
#define ZD 128
#define ED 64
#define N_ROWS (N_NODE * 4)

typedef unsigned long long u64t;

// ---------------- scratch (device globals: no allocation allowed) ----------------
__device__ float g_AB[N_NODE * 256];         // [node][0:128]=A, [128:256]=B
__device__ float g_E2[N_ROWS * HID];         // e-branch output per (node,orb)
__device__ float g_W1T[128 * 256];           // Weff[k][c]
__device__ float g_W2T[128 * 128];           // zW2[n][k] -> [k][n]
__device__ float g_We1T[64 * 128];           // eW1[n][k] -> [k][n]
__device__ float g_We2T[128 * 128];          // eW2[n][k] -> [k][n]

__device__ __forceinline__ float silu_f(float x) {
    return x * __fdividef(1.0f, 1.0f + __expf(-x));
}

// ---------------- packed fp32x2 helpers (Blackwell FFMA2) ----------------
__device__ __forceinline__ u64t pk2(float lo, float hi) {
    u64t r;
    asm("mov.b64 %0, {%1, %2};" : "=l"(r) : "f"(lo), "f"(hi));
    return r;
}
__device__ __forceinline__ void fma2(u64t& d, u64t a, u64t b) {
    asm("fma.rn.f32x2 %0, %1, %2, %0;" : "+l"(d) : "l"(a), "l"(b));
}
__device__ __forceinline__ float2 up2(u64t v) {
    float2 f;
    asm("mov.b64 {%0, %1}, %2;" : "=f"(f.x), "=f"(f.y) : "l"(v));
    return f;
}

// ---------------- kernel 0: weight transposes ----------------
__global__ void prep_kernel(const float* __restrict__ zW1,
                            const float* __restrict__ zW2,
                            const float* __restrict__ eW1,
                            const float* __restrict__ eW2) {
    int i = blockIdx.x * blockDim.x + threadIdx.x;
    if (i < 32768) {                       // g_W1T: 128 k x 256 c
        int k = i >> 8, c = i & 255;
        g_W1T[i] = (c < 128) ? zW1[c * 256 + k] : zW1[(c - 128) * 256 + 128 + k];
    } else if (i < 49152) {                // g_W2T
        int q = i - 32768; int k = q >> 7, n = q & 127;
        g_W2T[q] = zW2[n * 128 + k];
    } else if (i < 57344) {                // g_We1T (64 k x 128 n)
        int q = i - 49152; int k = q >> 7, n = q & 127;
        g_We1T[q] = eW1[n * 64 + k];
    } else if (i < 73728) {                // g_We2T
        int q = i - 57344; int k = q >> 7, n = q & 127;
        g_We2T[q] = eW2[n * 128 + k];
    }
}

// ---------------- kernel 1: per-node A|B = silu(z) @ W1eff^T ----------------
__global__ __launch_bounds__(256, 2)
void nodeAB_kernel(const float* __restrict__ z_embed) {
    extern __shared__ float sm[];
    float* sP = sm;            // [128][128]
    float* sW = sm + 16384;    // [64][132]
    const int tid = threadIdx.x;
    const int m0 = blockIdx.x * 128;
    const int half = blockIdx.y;

    #pragma unroll
    for (int it = 0; it < 16; ++it) {
        int m = it * 8 + (tid >> 5);
        int k4 = (tid & 31) * 4;
        int node = m0 + m;
        float4 v = make_float4(0.f, 0.f, 0.f, 0.f);
        if (node < N_NODE) v = *reinterpret_cast<const float4*>(&z_embed[node * ZD + k4]);
        v.x = silu_f(v.x); v.y = silu_f(v.y); v.z = silu_f(v.z); v.w = silu_f(v.w);
        *reinterpret_cast<float4*>(&sP[m * 128 + k4]) = v;
    }

    const int ty = tid >> 4, tx = tid & 15;
    const int mB = ty * 8, nB = tx * 8;
    u64t acc[8][4];
    #pragma unroll
    for (int r = 0; r < 8; ++r)
        #pragma unroll
        for (int c = 0; c < 4; ++c) acc[r][c] = 0ULL;

    for (int c64 = 0; c64 < 2; ++c64) {
        if (c64) __syncthreads();
        #pragma unroll
        for (int it = 0; it < 8; ++it) {
            int kr = it * 8 + (tid >> 5);
            int n4 = (tid & 31) * 4;
            float4 w = *reinterpret_cast<const float4*>(
                &g_W1T[(c64 * 64 + kr) * 256 + half * 128 + n4]);
            *reinterpret_cast<float4*>(&sW[kr * 132 + n4]) = w;
        }
        __syncthreads();
        #pragma unroll 4
        for (int k = 0; k < 64; ++k) {
            u64t bb0 = *reinterpret_cast<const u64t*>(&sW[k * 132 + nB]);
            u64t bb1 = *reinterpret_cast<const u64t*>(&sW[k * 132 + nB + 2]);
            u64t bb2 = *reinterpret_cast<const u64t*>(&sW[k * 132 + nB + 4]);
            u64t bb3 = *reinterpret_cast<const u64t*>(&sW[k * 132 + nB + 6]);
            #pragma unroll
            for (int r = 0; r < 8; ++r) {
                float av = sP[(mB + r) * 128 + c64 * 64 + k];
                u64t aa = pk2(av, av);
                fma2(acc[r][0], aa, bb0);
                fma2(acc[r][1], aa, bb1);
                fma2(acc[r][2], aa, bb2);
                fma2(acc[r][3], aa, bb3);
            }
        }
    }

    #pragma unroll
    for (int r = 0; r < 8; ++r) {
        int node = m0 + mB + r;
        if (node < N_NODE) {
            float2 v0 = up2(acc[r][0]), v1 = up2(acc[r][1]);
            float2 v2 = up2(acc[r][2]), v3 = up2(acc[r][3]);
            float4 o0 = make_float4(v0.x, v0.y, v1.x, v1.y);
            float4 o1 = make_float4(v2.x, v2.y, v3.x, v3.y);
            *reinterpret_cast<float4*>(&g_AB[node * 256 + half * 128 + nB]) = o0;
            *reinterpret_cast<float4*>(&g_AB[node * 256 + half * 128 + nB + 4]) = o1;
        }
    }
}

// ---------------- kernel 2: per-(node,orb) e-branch, fused 2 layers ----------------
__global__ __launch_bounds__(256, 1)
void nodeE_kernel(const float* __restrict__ e_embed) {
    extern __shared__ float sm[];
    float* sX  = sm;            // [128][64]
    float* sW1 = sm + 8192;     // [64][132]
    float* sH  = sm + 16640;    // [128][128]
    float* sW2 = sm + 33024;    // [128][132]
    const int tid = threadIdx.x;
    const int r0 = blockIdx.x * 128;

    #pragma unroll
    for (int it = 0; it < 8; ++it) {
        int m = it * 16 + (tid >> 4);
        int k4 = (tid & 15) * 4;
        int row = r0 + m;
        float4 v = make_float4(0.f, 0.f, 0.f, 0.f);
        if (row < N_ROWS) v = *reinterpret_cast<const float4*>(&e_embed[row * ED + k4]);
        v.x = silu_f(v.x); v.y = silu_f(v.y); v.z = silu_f(v.z); v.w = silu_f(v.w);
        *reinterpret_cast<float4*>(&sX[m * 64 + k4]) = v;
    }
    #pragma unroll
    for (int it = 0; it < 8; ++it) {
        int kr = it * 8 + (tid >> 5);
        int n4 = (tid & 31) * 4;
        float4 w = *reinterpret_cast<const float4*>(&g_We1T[kr * 128 + n4]);
        *reinterpret_cast<float4*>(&sW1[kr * 132 + n4]) = w;
    }
    #pragma unroll
    for (int it = 0; it < 16; ++it) {
        int kr = it * 8 + (tid >> 5);
        int n4 = (tid & 31) * 4;
        float4 w = *reinterpret_cast<const float4*>(&g_We2T[kr * 128 + n4]);
        *reinterpret_cast<float4*>(&sW2[kr * 132 + n4]) = w;
    }
    __syncthreads();

    const int ty = tid >> 4, tx = tid & 15;
    const int mB = ty * 8, nB = tx * 8;
    u64t acc[8][4];
    #pragma unroll
    for (int r = 0; r < 8; ++r)
        #pragma unroll
        for (int c = 0; c < 4; ++c) acc[r][c] = 0ULL;

    #pragma unroll 4
    for (int k = 0; k < 64; ++k) {                  // layer 1
        u64t bb0 = *reinterpret_cast<const u64t*>(&sW1[k * 132 + nB]);
        u64t bb1 = *reinterpret_cast<const u64t*>(&sW1[k * 132 + nB + 2]);
        u64t bb2 = *reinterpret_cast<const u64t*>(&sW1[k * 132 + nB + 4]);
        u64t bb3 = *reinterpret_cast<const u64t*>(&sW1[k * 132 + nB + 6]);
        #pragma unroll
        for (int r = 0; r < 8; ++r) {
            float av = sX[(mB + r) * 64 + k];
            u64t aa = pk2(av, av);
            fma2(acc[r][0], aa, bb0);
            fma2(acc[r][1], aa, bb1);
            fma2(acc[r][2], aa, bb2);
            fma2(acc[r][3], aa, bb3);
        }
    }

    #pragma unroll
    for (int r = 0; r < 8; ++r) {                   // sH = silu(layer1)
        float2 v0 = up2(acc[r][0]), v1 = up2(acc[r][1]);
        float2 v2 = up2(acc[r][2]), v3 = up2(acc[r][3]);
        float4 h0, h1;
        h0.x = silu_f(v0.x); h0.y = silu_f(v0.y); h0.z = silu_f(v1.x); h0.w = silu_f(v1.y);
        h1.x = silu_f(v2.x); h1.y = silu_f(v2.y); h1.z = silu_f(v3.x); h1.w = silu_f(v3.y);
        *reinterpret_cast<float4*>(&sH[(mB + r) * 128 + nB]) = h0;
        *reinterpret_cast<float4*>(&sH[(mB + r) * 128 + nB + 4]) = h1;
    }
    __syncthreads();

    u64t acc2[8][4];
    #pragma unroll
    for (int r = 0; r < 8; ++r)
        #pragma unroll
        for (int c = 0; c < 4; ++c) acc2[r][c] = 0ULL;

    #pragma unroll 4
    for (int k = 0; k < 128; ++k) {                 // layer 2
        u64t bb0 = *reinterpret_cast<const u64t*>(&sW2[k * 132 + nB]);
        u64t bb1 = *reinterpret_cast<const u64t*>(&sW2[k * 132 + nB + 2]);
        u64t bb2 = *reinterpret_cast<const u64t*>(&sW2[k * 132 + nB + 4]);
        u64t bb3 = *reinterpret_cast<const u64t*>(&sW2[k * 132 + nB + 6]);
        #pragma unroll
        for (int r = 0; r < 8; ++r) {
            float av = sH[(mB + r) * 128 + k];
            u64t aa = pk2(av, av);
            fma2(acc2[r][0], aa, bb0);
            fma2(acc2[r][1], aa, bb1);
            fma2(acc2[r][2], aa, bb2);
            fma2(acc2[r][3], aa, bb3);
        }
    }

    #pragma unroll
    for (int r = 0; r < 8; ++r) {
        int row = r0 + mB + r;
        if (row < N_ROWS) {
            float2 v0 = up2(acc2[r][0]), v1 = up2(acc2[r][1]);
            float2 v2 = up2(acc2[r][2]), v3 = up2(acc2[r][3]);
            float4 o0 = make_float4(v0.x, v0.y, v1.x, v1.y);
            float4 o1 = make_float4(v2.x, v2.y, v3.x, v3.y);
            *reinterpret_cast<float4*>(&g_E2[row * 128 + nB]) = o0;
            *reinterpret_cast<float4*>(&g_E2[row * 128 + nB + 4]) = o1;
        }
    }
}

// ---------------- kernel 3: per-edge second layer + epilogue ----------------
__global__ __launch_bounds__(256, 2)
void edge_kernel(const int* __restrict__ idx_i, const int* __restrict__ idx_j,
                 const float* __restrict__ zb1, const float* __restrict__ zb2,
                 float* __restrict__ out) {
    extern __shared__ float sm[];
    float* sS  = sm;            // [128][128]  s tile; later reused as g
    float* sW  = sm + 16384;    // [64][132] -> ends 24832
    float* sB2 = sm + 24832;    // [128]
    int*   sJ  = reinterpret_cast<int*>(sm + 24960);  // [128] -> ends 25088
    const int tid = threadIdx.x;
    const int e0 = blockIdx.x * 128;

    if (tid < 128) {
        sB2[tid] = zb2[tid];
        sJ[tid] = idx_j[e0 + tid];
    }

    // build s tile
    #pragma unroll
    for (int it = 0; it < 16; ++it) {
        int m = it * 8 + (tid >> 5);
        int k4 = (tid & 31) * 4;
        int e = e0 + m;
        int i = __ldg(&idx_i[e]);
        int j = __ldg(&idx_j[e]);
        float4 a = *reinterpret_cast<const float4*>(&g_AB[i * 256 + k4]);
        float4 b = *reinterpret_cast<const float4*>(&g_AB[j * 256 + 128 + k4]);
        float4 bias = __ldg(reinterpret_cast<const float4*>(&zb1[k4]));
        float4 s;
        s.x = silu_f(a.x + b.x + bias.x);
        s.y = silu_f(a.y + b.y + bias.y);
        s.z = silu_f(a.z + b.z + bias.z);
        s.w = silu_f(a.w + b.w + bias.w);
        *reinterpret_cast<float4*>(&sS[m * 128 + k4]) = s;
    }

    const int ty = tid >> 4, tx = tid & 15;
    const int mB = ty * 8, nB = tx * 8;
    u64t acc[8][4];
    #pragma unroll
    for (int r = 0; r < 8; ++r)
        #pragma unroll
        for (int c = 0; c < 4; ++c) acc[r][c] = 0ULL;

    for (int c64 = 0; c64 < 2; ++c64) {
        if (c64) __syncthreads();
        #pragma unroll
        for (int it = 0; it < 8; ++it) {
            int kr = it * 8 + (tid >> 5);
            int n4 = (tid & 31) * 4;
            float4 w = *reinterpret_cast<const float4*>(&g_W2T[(c64 * 64 + kr) * 128 + n4]);
            *reinterpret_cast<float4*>(&sW[kr * 132 + n4]) = w;
        }
        __syncthreads();
        #pragma unroll 4
        for (int k = 0; k < 64; ++k) {
            u64t bb0 = *reinterpret_cast<const u64t*>(&sW[k * 132 + nB]);
            u64t bb1 = *reinterpret_cast<const u64t*>(&sW[k * 132 + nB + 2]);
            u64t bb2 = *reinterpret_cast<const u64t*>(&sW[k * 132 + nB + 4]);
            u64t bb3 = *reinterpret_cast<const u64t*>(&sW[k * 132 + nB + 6]);
            #pragma unroll
            for (int r = 0; r < 8; ++r) {
                float av = sS[(mB + r) * 128 + c64 * 64 + k];
                u64t aa = pk2(av, av);
                fma2(acc[r][0], aa, bb0);
                fma2(acc[r][1], aa, bb1);
                fma2(acc[r][2], aa, bb2);
                fma2(acc[r][3], aa, bb3);
            }
        }
    }
    __syncthreads();    // done reading sS -> safe to overwrite with g

    // g = 1 + z2 + zb2
    #pragma unroll
    for (int r = 0; r < 8; ++r) {
        float2 v0 = up2(acc[r][0]), v1 = up2(acc[r][1]);
        float2 v2 = up2(acc[r][2]), v3 = up2(acc[r][3]);
        float4 g0, g1;
        g0.x = 1.f + v0.x + sB2[nB + 0];
        g0.y = 1.f + v0.y + sB2[nB + 1];
        g0.z = 1.f + v1.x + sB2[nB + 2];
        g0.w = 1.f + v1.y + sB2[nB + 3];
        g1.x = 1.f + v2.x + sB2[nB + 4];
        g1.y = 1.f + v2.y + sB2[nB + 5];
        g1.z = 1.f + v3.x + sB2[nB + 6];
        g1.w = 1.f + v3.y + sB2[nB + 7];
        *reinterpret_cast<float4*>(&sS[(mB + r) * 128 + nB]) = g0;
        *reinterpret_cast<float4*>(&sS[(mB + r) * 128 + nB + 4]) = g1;
    }
    __syncthreads();

    // epilogue: out[e, orb, h] = E2[j, orb, h] * g[e, h]
    const int h = (tid & 31) * 4;
    const int orb = (tid >> 5) & 3;
    #pragma unroll 4
    for (int it = 0; it < 64; ++it) {
        int m = it * 2 + (tid >> 7);
        int j = sJ[m];
        float4 ev = *reinterpret_cast<const float4*>(&g_E2[(j * 4 + orb) * 128 + h]);
        float4 g  = *reinterpret_cast<const float4*>(&sS[m * 128 + h]);
        float4 o;
        o.x = ev.x * g.x; o.y = ev.y * g.y; o.z = ev.z * g.z; o.w = ev.w * g.w;
        size_t off = ((size_t)(e0 + m) * 4 + orb) * 128 + h;
        __stcs(reinterpret_cast<float4*>(&out[off]), o);
    }
}

// ---------------- launch ----------------
extern "C" void kernel_launch(void* const* d_in, const int* in_sizes, int n_in,
                              void* d_out, int out_size) {
    const float* z_embed = (const float*)d_in[0];
    const float* e_embed = (const float*)d_in[1];
    const int*   idx_i   = (const int*)d_in[2];
    const int*   idx_j   = (const int*)d_in[3];
    const float* zW1     = (const float*)d_in[4];
    const float* zb1     = (const float*)d_in[5];
    const float* zW2     = (const float*)d_in[6];
    const float* zb2     = (const float*)d_in[7];
    const float* eW1     = (const float*)d_in[8];
    const float* eW2     = (const float*)d_in[9];
    float* out = (float*)d_out;

    const int SMEM1 = (16384 + 64 * 132) * 4;                    //  99328 B
    const int SMEM2 = (8192 + 64 * 132 + 16384 + 128 * 132) * 4; // 199680 B
    const int SMEM3 = (16384 + 64 * 132 + 128 + 128) * 4;        // 100352 B
    cudaFuncSetAttribute(nodeAB_kernel, cudaFuncAttributeMaxDynamicSharedMemorySize, SMEM1);
    cudaFuncSetAttribute(nodeE_kernel,  cudaFuncAttributeMaxDynamicSharedMemorySize, SMEM2);
    cudaFuncSetAttribute(edge_kernel,   cudaFuncAttributeMaxDynamicSharedMemorySize, SMEM3);

    prep_kernel<<<288, 256>>>(zW1, zW2, eW1, eW2);
    nodeAB_kernel<<<dim3(391, 2), 256, SMEM1>>>(z_embed);
    nodeE_kernel<<<1563, 256, SMEM2>>>(e_embed);
    edge_kernel<<<6250, 256, SMEM3>>>(idx_i, idx_j, zb1, zb2, out);
}